// round 9
// baseline (speedup 1.0000x reference)
#include <cuda_runtime.h>

// SSIM loss, fused separable 11x11 Gaussian, B=16 C=3 H=512 W=512 fp32.
// v9: 4-CTA/SM occupancy via smem raw ring + shared-product vertical conv.
//   grid = (12 chunks, 48 planes) = 576 blocks ~= 148 SM x 4 CTAs.
//   128 thr, 4 cols/thread. Per iteration: TWO output rows.
//   Raw data: 6-row per-thread-private smem ring (no barriers needed) +
//   5-row register ring + prefetch. Vertical conv streams over the 12
//   source rows, computing products (a^2+b^2, ab) ONCE per source row and
//   accumulating into both output rows (20% fewer fma than row-at-a-time).
//   Horizontal conv: scalar FFMA-imm from single-set padded vsbuf
//   (2 barriers per 2 rows). Finalize folded into last block.

#define HH 512
#define WW 512
#define NTHREADS 128
#define NPIX 12582912.0
#define GX 12
#define GY 48
#define NBLOCKS (GX * GY)

typedef unsigned long long u64;

__device__ constexpr float KW[11] = {
    0.00102839f, 0.00759876f, 0.03600077f, 0.10936069f, 0.21300554f,
    0.26601172f,
    0.21300554f, 0.10936069f, 0.03600077f, 0.00759876f, 0.00102839f};

__device__ double g_partial[NBLOCKS];
__device__ unsigned g_count = 0;

// ---- f32x2 packed helpers (sm_100+ PTX) ----
__device__ __forceinline__ u64 pk2(float lo, float hi) {
    u64 r; asm("mov.b64 %0, {%1, %2};" : "=l"(r) : "f"(lo), "f"(hi)); return r;
}
__device__ __forceinline__ void upk2(u64 v, float& lo, float& hi) {
    asm("mov.b64 {%0, %1}, %2;" : "=f"(lo), "=f"(hi) : "l"(v));
}
__device__ __forceinline__ u64 f2add(u64 a, u64 b) {
    u64 r; asm("add.rn.f32x2 %0, %1, %2;" : "=l"(r) : "l"(a), "l"(b)); return r;
}
__device__ __forceinline__ u64 f2mul(u64 a, u64 b) {
    u64 r; asm("mul.rn.f32x2 %0, %1, %2;" : "=l"(r) : "l"(a), "l"(b)); return r;
}
__device__ __forceinline__ u64 f2fma(u64 a, u64 b, u64 c) {
    u64 r; asm("fma.rn.f32x2 %0, %1, %2, %3;" : "=l"(r) : "l"(a), "l"(b), "l"(c));
    return r;
}

__device__ __forceinline__ void load_row_pk(const float* __restrict__ p,
                                            int row, int c0, u64 o[2]) {
    if ((unsigned)row < (unsigned)HH) {
        ulonglong2 v = *reinterpret_cast<const ulonglong2*>(p + row * WW + c0);
        o[0] = v.x;
        o[1] = v.y;
    } else {
        o[0] = 0ull; o[1] = 0ull;
    }
}

__global__ __launch_bounds__(NTHREADS, 4)
void ssim_kernel(const float* __restrict__ sr, const float* __restrict__ hr,
                 float* __restrict__ out) {
    const int plane = blockIdx.y;
    const int bx = blockIdx.x;
    // chunks (all even, sum 512): first 4 = 44 rows, next 8 = 42 rows
    const int r0 = (bx < 4) ? 44 * bx : (176 + 42 * (bx - 4));
    const int npairs = (bx < 4) ? 22 : 21;
    const int tid = threadIdx.x;
    const int c0 = tid * 4;

    const float* __restrict__ pa = sr + (size_t)plane * HH * WW;
    const float* __restrict__ pb = hr + (size_t)plane * HH * WW;

    // Per-thread-private raw row ring: 6 rows (rows i-5..i+0 for pair i,i+1).
    // Each thread only touches its own 4 columns -> no barriers needed.
    __shared__ __align__(16) float rawA[6][WW];
    __shared__ __align__(16) float rawB[6][WW];
    // Single-set line buffer: 2 output rows x 4 fields; data col c at word
    // c+8, halo zeros at words [0..7] and [520..527].
    __shared__ __align__(16) float vsbuf[2][4][528];

    // halo init: 2 rows * 4 fields * 16 words = 128 entries, one per thread
    {
        int r = tid >> 6;
        int f = (tid >> 4) & 3;
        int k = tid & 15;
        int idx = (k < 8) ? k : (512 + k);
        vsbuf[r][f][idx] = 0.f;
    }

    // Packed weight constants (symmetric kernel -> 6 uniques).
    u64 WKP[6];
#pragma unroll
    for (int k = 0; k < 6; ++k) WKP[k] = pk2(KW[k], KW[k]);

    // ---- prologue ----
    // smem ring: rows r0-5 .. r0+0 at slot (r+600)%6
#pragma unroll
    for (int s = 0; s < 6; ++s) {
        int r = r0 - 5 + s;
        int slot = (r + 600) % 6;
        u64 t[2];
        load_row_pk(pa, r, c0, t);
        *reinterpret_cast<ulonglong2*>(&rawA[slot][c0]) =
            make_ulonglong2(t[0], t[1]);
        load_row_pk(pb, r, c0, t);
        *reinterpret_cast<ulonglong2*>(&rawB[slot][c0]) =
            make_ulonglong2(t[0], t[1]);
    }
    // register ring: rows r0+1 .. r0+5
    u64 ea[5][2], eb[5][2], na[2], nb[2];
#pragma unroll
    for (int k = 0; k < 5; ++k) {
        load_row_pk(pa, r0 + 1 + k, c0, ea[k]);
        load_row_pk(pb, r0 + 1 + k, c0, eb[k]);
    }
    load_row_pk(pa, r0 + 6, c0, na);
    load_row_pk(pb, r0 + 6, c0, nb);

    int slot0 = ((r0 - 5) % 6 + 6) % 6;  // slot of row i-5

    __syncthreads();  // halo init visible (once)

    const u64 TWO  = pk2(2.f, 2.f);
    const u64 NEG1 = pk2(-1.f, -1.f);
    const u64 C1   = pk2(1e-4f, 1e-4f);
    const u64 C2   = pk2(9e-4f, 9e-4f);

    float acc = 0.f;

#pragma unroll 1
    for (int p = 0; p < npairs; ++p) {
        const int i = r0 + 2 * p;

        // early prefetch rows i+7, i+8 (consumed at iteration end)
        u64 t7a[2], t7b[2], t8a[2], t8b[2];
        load_row_pk(pa, i + 7, c0, t7a);
        load_row_pk(pb, i + 7, c0, t7b);
        load_row_pk(pa, i + 8, c0, t8a);
        load_row_pk(pb, i + 8, c0, t8b);

        // ---- vertical conv, streamed over 12 source rows ----
        // A = output row i (taps s=0..10, weight KW[s])
        // B = output row i+1 (taps s=1..11, weight KW[s-1])
        // fields: 0=mu1, 1=mu2, 2=q(a^2+b^2), 3=p(ab)
        u64 A[4][2], B[4][2];
#pragma unroll
        for (int s = 0; s < 12; ++s) {
            u64 a[2], b[2];
            if (s < 6) {
                int sl = slot0 + s;
                if (sl >= 6) sl -= 6;
                ulonglong2 ta =
                    *reinterpret_cast<const ulonglong2*>(&rawA[sl][c0]);
                ulonglong2 tb =
                    *reinterpret_cast<const ulonglong2*>(&rawB[sl][c0]);
                a[0] = ta.x; a[1] = ta.y;
                b[0] = tb.x; b[1] = tb.y;
            } else if (s < 11) {
#pragma unroll
                for (int q = 0; q < 2; ++q) { a[q] = ea[s - 6][q]; b[q] = eb[s - 6][q]; }
            } else {
#pragma unroll
                for (int q = 0; q < 2; ++q) { a[q] = na[q]; b[q] = nb[q]; }
            }
#pragma unroll
            for (int q = 0; q < 2; ++q) {
                // shared products for this source row
                u64 qrow = f2fma(b[q], b[q], f2mul(a[q], a[q]));
                u64 ab   = f2mul(a[q], b[q]);
                if (s <= 10) {
                    const int wi = (s <= 5) ? s : (10 - s);
                    if (s == 0) {
                        A[0][q] = f2mul(WKP[wi], a[q]);
                        A[1][q] = f2mul(WKP[wi], b[q]);
                        A[2][q] = f2mul(WKP[wi], qrow);
                        A[3][q] = f2mul(WKP[wi], ab);
                    } else {
                        A[0][q] = f2fma(WKP[wi], a[q], A[0][q]);
                        A[1][q] = f2fma(WKP[wi], b[q], A[1][q]);
                        A[2][q] = f2fma(WKP[wi], qrow, A[2][q]);
                        A[3][q] = f2fma(WKP[wi], ab, A[3][q]);
                    }
                }
                if (s >= 1) {
                    const int k1 = s - 1;
                    const int wi = (k1 <= 5) ? k1 : (10 - k1);
                    if (s == 1) {
                        B[0][q] = f2mul(WKP[wi], a[q]);
                        B[1][q] = f2mul(WKP[wi], b[q]);
                        B[2][q] = f2mul(WKP[wi], qrow);
                        B[3][q] = f2mul(WKP[wi], ab);
                    } else {
                        B[0][q] = f2fma(WKP[wi], a[q], B[0][q]);
                        B[1][q] = f2fma(WKP[wi], b[q], B[1][q]);
                        B[2][q] = f2fma(WKP[wi], qrow, B[2][q]);
                        B[3][q] = f2fma(WKP[wi], ab, B[3][q]);
                    }
                }
            }
        }

        // retire rows i+1, i+2 (reg ring pos 0,1) into freed slots
        // slot(i+1) == slot(i-5) == slot0 ; slot(i+2) == slot0+1 (wrapped)
        {
            int sl1 = slot0;
            int sl2 = slot0 + 1; if (sl2 >= 6) sl2 -= 6;
            *reinterpret_cast<ulonglong2*>(&rawA[sl1][c0]) =
                make_ulonglong2(ea[0][0], ea[0][1]);
            *reinterpret_cast<ulonglong2*>(&rawB[sl1][c0]) =
                make_ulonglong2(eb[0][0], eb[0][1]);
            *reinterpret_cast<ulonglong2*>(&rawA[sl2][c0]) =
                make_ulonglong2(ea[1][0], ea[1][1]);
            *reinterpret_cast<ulonglong2*>(&rawB[sl2][c0]) =
                make_ulonglong2(eb[1][0], eb[1][1]);
        }
        slot0 += 2; if (slot0 >= 6) slot0 -= 6;

        // publish vertical sums (one STS.128 per field per row)
#pragma unroll
        for (int f = 0; f < 4; ++f) {
            *reinterpret_cast<ulonglong2*>(&vsbuf[0][f][8 + c0]) =
                make_ulonglong2(A[f][0], A[f][1]);
            *reinterpret_cast<ulonglong2*>(&vsbuf[1][f][8 + c0]) =
                make_ulonglong2(B[f][0], B[f][1]);
        }

        // advance register ring (rows i+3..i+7) + prefetch (i+8)
#pragma unroll
        for (int q = 0; q < 2; ++q) {
            ea[0][q] = ea[2][q]; eb[0][q] = eb[2][q];
            ea[1][q] = ea[3][q]; eb[1][q] = eb[3][q];
            ea[2][q] = ea[4][q]; eb[2][q] = eb[4][q];
            ea[3][q] = na[q];    eb[3][q] = nb[q];
            ea[4][q] = t7a[q];   eb[4][q] = t7b[q];
            na[q] = t8a[q];      nb[q] = t8b[q];
        }

        __syncthreads();  // vsbuf writes visible to all

        // ---- horizontal conv + map, rows 0 and 1 (scalar FFMA-imm) ----
#pragma unroll
        for (int r = 0; r < 2; ++r) {
            float cv[4][4];
#pragma unroll
            for (int f = 0; f < 4; ++f) {
                float v[20];
#pragma unroll
                for (int q5 = 0; q5 < 5; ++q5) {
                    float4 t = *reinterpret_cast<const float4*>(
                        &vsbuf[r][f][c0 + 4 * q5]);
                    v[4 * q5 + 0] = t.x; v[4 * q5 + 1] = t.y;
                    v[4 * q5 + 2] = t.z; v[4 * q5 + 3] = t.w;
                }
#pragma unroll
                for (int j = 0; j < 4; ++j) {
                    float s = KW[5] * v[8 + j];
#pragma unroll
                    for (int k = 0; k < 11; ++k) {
                        if (k == 5) continue;
                        s += KW[k] * v[3 + j + k];
                    }
                    cv[f][j] = s;
                }
            }
#pragma unroll
            for (int q = 0; q < 2; ++q) {
                u64 m1 = pk2(cv[0][2 * q], cv[0][2 * q + 1]);
                u64 m2 = pk2(cv[1][2 * q], cv[1][2 * q + 1]);
                u64 q2 = pk2(cv[2][2 * q], cv[2][2 * q + 1]);
                u64 rr = pk2(cv[3][2 * q], cv[3][2 * q + 1]);
                u64 m12 = f2mul(m1, m2);
                u64 sms = f2fma(m2, m2, f2mul(m1, m1));
                u64 num1 = f2fma(TWO, m12, C1);
                u64 sig12 = f2fma(m12, NEG1, rr);
                u64 num2 = f2fma(TWO, sig12, C2);
                u64 den1 = f2add(sms, C1);
                u64 den2 = f2add(f2fma(sms, NEG1, q2), C2);
                u64 num = f2mul(num1, num2);
                u64 den = f2mul(den1, den2);
                float n0, n1, d0, d1;
                upk2(num, n0, n1);
                upk2(den, d0, d1);
                acc += __fdividef(n0, d0);
                acc += __fdividef(n1, d1);
            }
        }

        __syncthreads();  // vsbuf consumed before next iteration's writes
    }

    // block reduction -> per-block partial
#pragma unroll
    for (int o = 16; o > 0; o >>= 1)
        acc += __shfl_down_sync(0xFFFFFFFFu, acc, o);

    __shared__ float wsum[4];
    __shared__ int is_last;
    if ((tid & 31) == 0) wsum[tid >> 5] = acc;
    __syncthreads();
    if (tid == 0) {
        double s = (double)wsum[0] + (double)wsum[1] + (double)wsum[2] +
                   (double)wsum[3];
        g_partial[blockIdx.y * GX + blockIdx.x] = s;
        __threadfence();
        unsigned old = atomicInc(&g_count, NBLOCKS - 1);  // wraps to 0
        is_last = (old == NBLOCKS - 1);
    }
    __syncthreads();

    // last block finalizes (replay-deterministic: counter wraps to 0)
    if (is_last) {
        __threadfence();
        double s = 0.0;
        for (int i2 = tid; i2 < NBLOCKS; i2 += NTHREADS)
            s += __ldcg(&g_partial[i2]);
#pragma unroll
        for (int o = 16; o > 0; o >>= 1)
            s += __shfl_down_sync(0xFFFFFFFFu, s, o);
        __shared__ double dsm[4];
        if ((tid & 31) == 0) dsm[tid >> 5] = s;
        __syncthreads();
        if (tid == 0) {
            double tot = dsm[0] + dsm[1] + dsm[2] + dsm[3];
            out[0] = (float)(1.0 - tot / NPIX);
        }
    }
}

extern "C" void kernel_launch(void* const* d_in, const int* in_sizes, int n_in,
                              void* d_out, int out_size) {
    const float* sr = (const float*)d_in[0];
    const float* hr = (const float*)d_in[1];
    float* out = (float*)d_out;

    dim3 grid(GX, GY);
    ssim_kernel<<<grid, NTHREADS>>>(sr, hr, out);
}

// round 10
// speedup vs baseline: 1.2367x; 1.2367x over previous
#include <cuda_runtime.h>

// SSIM loss, fused separable 11x11 Gaussian, B=16 C=3 H=512 W=512 fp32.
// v10 = v7 skeleton + shared-product vertical conv (registers only).
//   grid = (9 chunks, 48 planes) = 432 blocks, 128 thr, 4 cols/thread,
//   3 CTAs/SM. Per iteration: TWO output rows from a 12-row REGISTER ring.
//   Vertical conv streams the 12 source rows, computing (a^2+b^2) and (ab)
//   ONCE per source row, accumulating into both output rows (-16% fma).
//   Horizontal conv: scalar FFMA-imm from quad-buffered padded smem;
//   ONE __syncthreads per 2 rows. Finalize folded into last block.

#define HH 512
#define WW 512
#define NTHREADS 128
#define NPIX 12582912.0
#define GX 9
#define GY 48
#define NBLOCKS (GX * GY)

typedef unsigned long long u64;

__device__ constexpr float KW[11] = {
    0.00102839f, 0.00759876f, 0.03600077f, 0.10936069f, 0.21300554f,
    0.26601172f,
    0.21300554f, 0.10936069f, 0.03600077f, 0.00759876f, 0.00102839f};

__device__ double g_partial[NBLOCKS];
__device__ unsigned g_count = 0;

// ---- f32x2 packed helpers (sm_100+ PTX) ----
__device__ __forceinline__ u64 pk2(float lo, float hi) {
    u64 r; asm("mov.b64 %0, {%1, %2};" : "=l"(r) : "f"(lo), "f"(hi)); return r;
}
__device__ __forceinline__ void upk2(u64 v, float& lo, float& hi) {
    asm("mov.b64 {%0, %1}, %2;" : "=f"(lo), "=f"(hi) : "l"(v));
}
__device__ __forceinline__ u64 f2add(u64 a, u64 b) {
    u64 r; asm("add.rn.f32x2 %0, %1, %2;" : "=l"(r) : "l"(a), "l"(b)); return r;
}
__device__ __forceinline__ u64 f2mul(u64 a, u64 b) {
    u64 r; asm("mul.rn.f32x2 %0, %1, %2;" : "=l"(r) : "l"(a), "l"(b)); return r;
}
__device__ __forceinline__ u64 f2fma(u64 a, u64 b, u64 c) {
    u64 r; asm("fma.rn.f32x2 %0, %1, %2, %3;" : "=l"(r) : "l"(a), "l"(b), "l"(c));
    return r;
}

__device__ __forceinline__ void load_row_pk(const float* __restrict__ p,
                                            int row, int c0, u64 o[2]) {
    if ((unsigned)row < (unsigned)HH) {
        ulonglong2 v = *reinterpret_cast<const ulonglong2*>(p + row * WW + c0);
        o[0] = v.x;
        o[1] = v.y;
    } else {
        o[0] = 0ull; o[1] = 0ull;
    }
}

__global__ __launch_bounds__(NTHREADS, 3)
void ssim_kernel(const float* __restrict__ sr, const float* __restrict__ hr,
                 float* __restrict__ out) {
    const int plane = blockIdx.y;
    const int bx = blockIdx.x;
    // chunks: 58,58,58,58,56,56,56,56,56 (all even; sum = 512)
    const int r0 = (bx < 4) ? 58 * bx : (232 + 56 * (bx - 4));
    const int npairs = (bx < 4) ? 29 : 28;
    const int tid = threadIdx.x;
    const int c0 = tid * 4;

    const float* __restrict__ pa = sr + (size_t)plane * HH * WW;
    const float* __restrict__ pb = hr + (size_t)plane * HH * WW;

    // Quad-buffered line buffer: [buf 0..3][field 0..3], data col c at word
    // c+8, halo zeros at words [0..7] and [520..527].
    __shared__ __align__(16) float vsbuf[4][4][528];

    {
        // 4 bufs * 4 fields * 16 halo words = 256 inits, 2 per thread
        for (int q = tid; q < 256; q += NTHREADS) {
            int b = q >> 6;
            int f = (q >> 4) & 3;
            int k = q & 15;
            int idx = (k < 8) ? k : (512 + k);
            vsbuf[b][f][idx] = 0.f;
        }
    }
    __syncthreads();

    // Packed weight constants (symmetric kernel -> 6 uniques).
    u64 WKP[6];
#pragma unroll
    for (int k = 0; k < 6; ++k) WKP[k] = pk2(KW[k], KW[k]);

    // Register ring of packed raw rows: positions 0..11 hold source rows
    // (i-5) .. (i+6) for the current output pair (i, i+1).
    u64 ra[12][2], rb[12][2];
#pragma unroll
    for (int k = 0; k < 12; ++k) {
        load_row_pk(pa, r0 - 5 + k, c0, ra[k]);
        load_row_pk(pb, r0 - 5 + k, c0, rb[k]);
    }

    float acc = 0.f;

#pragma unroll 2
    for (int p = 0; p < npairs; ++p) {
        const int bufA = (p & 1) * 2;
        const int bufB = bufA + 1;
        const int i = r0 + 2 * p;

        // early prefetch rows i+7, i+8 (consumed at ring advance below)
        u64 t7a[2], t7b[2], t8a[2], t8b[2];
        load_row_pk(pa, i + 7, c0, t7a);
        load_row_pk(pb, i + 7, c0, t7b);
        load_row_pk(pa, i + 8, c0, t8a);
        load_row_pk(pb, i + 8, c0, t8b);

        // ---- vertical conv streamed over the 12 source rows ----
        // A = output row i   (taps s=0..10, weight KW[s])
        // B = output row i+1 (taps s=1..11, weight KW[s-1])
        // fields: 0=mu1, 1=mu2, 2=q(a^2+b^2), 3=p(ab)
        u64 A[4][2], B[4][2];
#pragma unroll
        for (int s = 0; s < 12; ++s) {
#pragma unroll
            for (int q = 0; q < 2; ++q) {
                u64 a = ra[s][q], b = rb[s][q];
                u64 qrow = f2fma(b, b, f2mul(a, a));
                u64 ab = f2mul(a, b);
                if (s <= 10) {
                    const int wi = (s <= 5) ? s : (10 - s);
                    if (s == 0) {
                        A[0][q] = f2mul(WKP[wi], a);
                        A[1][q] = f2mul(WKP[wi], b);
                        A[2][q] = f2mul(WKP[wi], qrow);
                        A[3][q] = f2mul(WKP[wi], ab);
                    } else {
                        A[0][q] = f2fma(WKP[wi], a, A[0][q]);
                        A[1][q] = f2fma(WKP[wi], b, A[1][q]);
                        A[2][q] = f2fma(WKP[wi], qrow, A[2][q]);
                        A[3][q] = f2fma(WKP[wi], ab, A[3][q]);
                    }
                }
                if (s >= 1) {
                    const int k1 = s - 1;
                    const int wi = (k1 <= 5) ? k1 : (10 - k1);
                    if (s == 1) {
                        B[0][q] = f2mul(WKP[wi], a);
                        B[1][q] = f2mul(WKP[wi], b);
                        B[2][q] = f2mul(WKP[wi], qrow);
                        B[3][q] = f2mul(WKP[wi], ab);
                    } else {
                        B[0][q] = f2fma(WKP[wi], a, B[0][q]);
                        B[1][q] = f2fma(WKP[wi], b, B[1][q]);
                        B[2][q] = f2fma(WKP[wi], qrow, B[2][q]);
                        B[3][q] = f2fma(WKP[wi], ab, B[3][q]);
                    }
                }
            }
        }

        // publish vertical sums (one STS.128 per field per row)
#pragma unroll
        for (int f = 0; f < 4; ++f) {
            *reinterpret_cast<ulonglong2*>(&vsbuf[bufA][f][8 + c0]) =
                make_ulonglong2(A[f][0], A[f][1]);
            *reinterpret_cast<ulonglong2*>(&vsbuf[bufB][f][8 + c0]) =
                make_ulonglong2(B[f][0], B[f][1]);
        }

        // advance ring by 2 rows; consume prefetched rows
#pragma unroll
        for (int k = 0; k < 10; ++k) {
#pragma unroll
            for (int q = 0; q < 2; ++q) {
                ra[k][q] = ra[k + 2][q];
                rb[k][q] = rb[k + 2][q];
            }
        }
#pragma unroll
        for (int q = 0; q < 2; ++q) {
            ra[10][q] = t7a[q]; rb[10][q] = t7b[q];
            ra[11][q] = t8a[q]; rb[11][q] = t8b[q];
        }

        __syncthreads();  // the only barrier per 2 rows

        // ---- horizontal conv + map, rows A and B (scalar FFMA-imm) ----
#pragma unroll
        for (int r = 0; r < 2; ++r) {
            const int buf = bufA + r;
            float cv[4][4];
#pragma unroll
            for (int f = 0; f < 4; ++f) {
                float v[20];
#pragma unroll
                for (int q5 = 0; q5 < 5; ++q5) {
                    float4 t = *reinterpret_cast<const float4*>(
                        &vsbuf[buf][f][c0 + 4 * q5]);
                    v[4 * q5 + 0] = t.x; v[4 * q5 + 1] = t.y;
                    v[4 * q5 + 2] = t.z; v[4 * q5 + 3] = t.w;
                }
#pragma unroll
                for (int j = 0; j < 4; ++j) {
                    float s = KW[5] * v[8 + j];
#pragma unroll
                    for (int k = 0; k < 11; ++k) {
                        if (k == 5) continue;
                        s += KW[k] * v[3 + j + k];
                    }
                    cv[f][j] = s;
                }
            }
#pragma unroll
            for (int q = 0; q < 2; ++q) {
                float m1a, m1b, m2a, m2b, qa, qb, pa2, pb2;
                m1a = cv[0][2 * q]; m1b = cv[0][2 * q + 1];
                m2a = cv[1][2 * q]; m2b = cv[1][2 * q + 1];
                qa = cv[2][2 * q];  qb = cv[2][2 * q + 1];
                pa2 = cv[3][2 * q]; pb2 = cv[3][2 * q + 1];
                // scalar map, two columns
                float m12 = m1a * m2a;
                float sms = fmaf(m1a, m1a, m2a * m2a);
                float num1 = fmaf(m12, 2.f, 1e-4f);
                float num2 = fmaf(pa2 - m12, 2.f, 9e-4f);
                float den1 = sms + 1e-4f;
                float den2 = (qa - sms) + 9e-4f;
                acc += __fdividef(num1 * num2, den1 * den2);
                float m12y = m1b * m2b;
                float smsy = fmaf(m1b, m1b, m2b * m2b);
                float num1y = fmaf(m12y, 2.f, 1e-4f);
                float num2y = fmaf(pb2 - m12y, 2.f, 9e-4f);
                float den1y = smsy + 1e-4f;
                float den2y = (qb - smsy) + 9e-4f;
                acc += __fdividef(num1y * num2y, den1y * den2y);
            }
        }
        // no trailing barrier: next pair writes the other buffer set; reuse
        // of this set is fenced by the next __syncthreads.
    }

    // block reduction -> per-block partial
#pragma unroll
    for (int o = 16; o > 0; o >>= 1)
        acc += __shfl_down_sync(0xFFFFFFFFu, acc, o);

    __shared__ float wsum[4];
    __shared__ int is_last;
    if ((tid & 31) == 0) wsum[tid >> 5] = acc;
    __syncthreads();
    if (tid == 0) {
        double s = (double)wsum[0] + (double)wsum[1] + (double)wsum[2] +
                   (double)wsum[3];
        g_partial[blockIdx.y * GX + blockIdx.x] = s;
        __threadfence();
        unsigned old = atomicInc(&g_count, NBLOCKS - 1);  // wraps to 0
        is_last = (old == NBLOCKS - 1);
    }
    __syncthreads();

    // last block finalizes (replay-deterministic: counter wraps to 0)
    if (is_last) {
        __threadfence();
        double s = 0.0;
        for (int i2 = tid; i2 < NBLOCKS; i2 += NTHREADS)
            s += __ldcg(&g_partial[i2]);
#pragma unroll
        for (int o = 16; o > 0; o >>= 1)
            s += __shfl_down_sync(0xFFFFFFFFu, s, o);
        __shared__ double dsm[4];
        if ((tid & 31) == 0) dsm[tid >> 5] = s;
        __syncthreads();
        if (tid == 0) {
            double tot = dsm[0] + dsm[1] + dsm[2] + dsm[3];
            out[0] = (float)(1.0 - tot / NPIX);
        }
    }
}

extern "C" void kernel_launch(void* const* d_in, const int* in_sizes, int n_in,
                              void* d_out, int out_size) {
    const float* sr = (const float*)d_in[0];
    const float* hr = (const float*)d_in[1];
    float* out = (float*)d_out;

    dim3 grid(GX, GY);
    ssim_kernel<<<grid, NTHREADS>>>(sr, hr, out);
}

// round 11
// speedup vs baseline: 1.4370x; 1.1620x over previous
#include <cuda_runtime.h>

// SSIM loss, fused separable 11x11 Gaussian, B=16 C=3 H=512 W=512 fp32.
// v11 = v7 + cp.async row staging (no mainloop LDG, no prefetch registers).
//   grid = (9 chunks, 48 planes) = 432 blocks, 128 thr, 4 cols/thread,
//   3 CTAs/SM. Register ring of 11 packed raw rows; incoming rows arrive
//   via cp.async.cg into a 2-slot smem staging ring issued 2 rows ahead
//   (~900 cyc coverage > DRAM 577). Staging columns are thread-private ->
//   consumed with cp.async.wait_group only, no barrier.
//   Vertical conv: packed f32x2, packed weight regs. Horizontal: scalar
//   FFMA-imm from quad-buffered padded smem, ONE __syncthreads per 2 rows.
//   Finalize folded into the last block (atomicInc wrap, replay-safe).

#define HH 512
#define WW 512
#define NTHREADS 128
#define NPIX 12582912.0
#define GX 9
#define GY 48
#define NBLOCKS (GX * GY)

typedef unsigned long long u64;

__device__ constexpr float KW[11] = {
    0.00102839f, 0.00759876f, 0.03600077f, 0.10936069f, 0.21300554f,
    0.26601172f,
    0.21300554f, 0.10936069f, 0.03600077f, 0.00759876f, 0.00102839f};

__device__ double g_partial[NBLOCKS];
__device__ unsigned g_count = 0;

// ---- f32x2 packed helpers (sm_100+ PTX) ----
__device__ __forceinline__ u64 pk2(float lo, float hi) {
    u64 r; asm("mov.b64 %0, {%1, %2};" : "=l"(r) : "f"(lo), "f"(hi)); return r;
}
__device__ __forceinline__ void upk2(u64 v, float& lo, float& hi) {
    asm("mov.b64 {%0, %1}, %2;" : "=f"(lo), "=f"(hi) : "l"(v));
}
__device__ __forceinline__ u64 f2add(u64 a, u64 b) {
    u64 r; asm("add.rn.f32x2 %0, %1, %2;" : "=l"(r) : "l"(a), "l"(b)); return r;
}
__device__ __forceinline__ u64 f2mul(u64 a, u64 b) {
    u64 r; asm("mul.rn.f32x2 %0, %1, %2;" : "=l"(r) : "l"(a), "l"(b)); return r;
}
__device__ __forceinline__ u64 f2fma(u64 a, u64 b, u64 c) {
    u64 r; asm("fma.rn.f32x2 %0, %1, %2, %3;" : "=l"(r) : "l"(a), "l"(b), "l"(c));
    return r;
}

// ---- cp.async helpers ----
__device__ __forceinline__ void cp16(unsigned dst, const float* src) {
    asm volatile("cp.async.cg.shared.global [%0], [%1], 16;"
                 :: "r"(dst), "l"(src));
}
#define CP_COMMIT() asm volatile("cp.async.commit_group;" ::: "memory")
#define CP_WAIT1()  asm volatile("cp.async.wait_group 1;" ::: "memory")

__device__ __forceinline__ void load_row_pk(const float* __restrict__ p,
                                            int row, int c0, u64 o[2]) {
    if ((unsigned)row < (unsigned)HH) {
        ulonglong2 v = *reinterpret_cast<const ulonglong2*>(p + row * WW + c0);
        o[0] = v.x;
        o[1] = v.y;
    } else {
        o[0] = 0ull; o[1] = 0ull;
    }
}

__global__ __launch_bounds__(NTHREADS, 3)
void ssim_kernel(const float* __restrict__ sr, const float* __restrict__ hr,
                 float* __restrict__ out) {
    const int plane = blockIdx.y;
    const int bx = blockIdx.x;
    // chunks: 58,58,58,58,56,56,56,56,56 (all even; sum = 512)
    const int r0 = (bx < 4) ? 58 * bx : (232 + 56 * (bx - 4));
    const int npairs = (bx < 4) ? 29 : 28;
    const int tid = threadIdx.x;
    const int c0 = tid * 4;

    const float* __restrict__ pa = sr + (size_t)plane * HH * WW;
    const float* __restrict__ pb = hr + (size_t)plane * HH * WW;

    // Quad-buffered line buffer: [buf 0..3][field 0..3], data col c at word
    // c+8, halo zeros at words [0..7] and [520..527].
    __shared__ __align__(16) float vsbuf[4][4][528];
    // cp.async staging: 2 slots (by incoming-row parity) x 2 tensors.
    __shared__ __align__(16) float stageA[2][WW];
    __shared__ __align__(16) float stageB[2][WW];

    {
        // 4 bufs * 4 fields * 16 halo words = 256 inits, 2 per thread
        for (int q = tid; q < 256; q += NTHREADS) {
            int b = q >> 6;
            int f = (q >> 4) & 3;
            int k = q & 15;
            int idx = (k < 8) ? k : (512 + k);
            vsbuf[b][f][idx] = 0.f;
        }
    }
    __syncthreads();

    // staging smem addresses for this thread's 16B
    unsigned sA[2], sB[2];
#pragma unroll
    for (int s = 0; s < 2; ++s) {
        sA[s] = (unsigned)__cvta_generic_to_shared(&stageA[s][c0]);
        sB[s] = (unsigned)__cvta_generic_to_shared(&stageB[s][c0]);
    }

    // Packed weight constants (symmetric kernel -> 6 uniques).
    u64 WKP[6];
#pragma unroll
    for (int k = 0; k < 6; ++k) WKP[k] = pk2(KW[k], KW[k]);

    // Register ring: ra[1..10] = rows r0-5 .. r0+4 (guarded LDG).
    u64 ra[11][2], rb[11][2];
#pragma unroll
    for (int k = 0; k < 10; ++k) {
        load_row_pk(pa, r0 - 5 + k, c0, ra[k + 1]);
        load_row_pk(pb, r0 - 5 + k, c0, rb[k + 1]);
    }

    // Prologue staging: rows r0+5 (slot parity (r0+5)&1) and r0+6.
    {
        int g5 = r0 + 5, g6 = r0 + 6;  // both < HH (r0 <= 456)
        cp16(sA[g5 & 1], pa + g5 * WW + c0);
        cp16(sB[g5 & 1], pb + g5 * WW + c0);
        CP_COMMIT();
        cp16(sA[g6 & 1], pa + g6 * WW + c0);
        cp16(sB[g6 & 1], pb + g6 * WW + c0);
        CP_COMMIT();
    }

    const u64 TWO  = pk2(2.f, 2.f);
    const u64 NEG1 = pk2(-1.f, -1.f);
    const u64 C1   = pk2(1e-4f, 1e-4f);
    const u64 C2   = pk2(9e-4f, 9e-4f);

    float acc = 0.f;

#pragma unroll 2
    for (int p = 0; p < npairs; ++p) {
        const int bufA = (p & 1) * 2;
        const int i = r0 + 2 * p;

        // ---------- two rows: consume staged, vertical conv ----------
#pragma unroll
        for (int r = 0; r < 2; ++r) {
            const int gr = i + 5 + r;        // incoming ring row
            const int slot = gr & 1;

            CP_WAIT1();  // staged row gr complete (issued 2 rows ago)
            ulonglong2 ta = *reinterpret_cast<const ulonglong2*>(&stageA[slot][c0]);
            ulonglong2 tb = *reinterpret_cast<const ulonglong2*>(&stageB[slot][c0]);
            if (gr >= HH) { ta.x = 0; ta.y = 0; tb.x = 0; tb.y = 0; }

            // shift ring, push incoming row
#pragma unroll
            for (int k = 0; k < 10; ++k) {
#pragma unroll
                for (int q = 0; q < 2; ++q) {
                    ra[k][q] = ra[k + 1][q];
                    rb[k][q] = rb[k + 1][q];
                }
            }
            ra[10][0] = ta.x; ra[10][1] = ta.y;
            rb[10][0] = tb.x; rb[10][1] = tb.y;

            // issue staging for row gr+2 (same slot parity), clamped
            {
                int rn = gr + 2;
                int rc = (rn < HH) ? rn : (HH - 1);
                const float* gpa = pa + rc * WW + c0;
                const float* gpb = pb + rc * WW + c0;
                cp16(sA[slot], gpa);
                cp16(sB[slot], gpb);
                CP_COMMIT();
            }

            // vertical 11-tap conv, packed; center tap initializes.
            u64 s0[2], s1[2], sqa[2], sqb[2], srr[2];
#pragma unroll
            for (int q = 0; q < 2; ++q) {
                u64 a = ra[5][q], b = rb[5][q];
                u64 wa = f2mul(WKP[5], a);
                u64 wb = f2mul(WKP[5], b);
                s0[q] = wa; s1[q] = wb;
                sqa[q] = f2mul(wa, a);
                sqb[q] = f2mul(wb, b);
                srr[q] = f2mul(wa, b);
            }
#pragma unroll
            for (int k = 0; k < 11; ++k) {
                if (k == 5) continue;
                const int wi = (k < 5) ? k : (10 - k);
#pragma unroll
                for (int q = 0; q < 2; ++q) {
                    u64 a = ra[k][q], b = rb[k][q];
                    u64 wa = f2mul(WKP[wi], a);
                    u64 wb = f2mul(WKP[wi], b);
                    s0[q]  = f2add(s0[q], wa);
                    s1[q]  = f2add(s1[q], wb);
                    sqa[q] = f2fma(wa, a, sqa[q]);
                    sqb[q] = f2fma(wb, b, sqb[q]);
                    srr[q] = f2fma(wa, b, srr[q]);
                }
            }

            // publish vertical sums (one STS.128 per field)
            const int buf = bufA + r;
            *reinterpret_cast<ulonglong2*>(&vsbuf[buf][0][8 + c0]) =
                make_ulonglong2(s0[0], s0[1]);
            *reinterpret_cast<ulonglong2*>(&vsbuf[buf][1][8 + c0]) =
                make_ulonglong2(s1[0], s1[1]);
            *reinterpret_cast<ulonglong2*>(&vsbuf[buf][2][8 + c0]) =
                make_ulonglong2(f2add(sqa[0], sqb[0]), f2add(sqa[1], sqb[1]));
            *reinterpret_cast<ulonglong2*>(&vsbuf[buf][3][8 + c0]) =
                make_ulonglong2(srr[0], srr[1]);
        }

        __syncthreads();  // the only barrier per 2 rows

        // ---------- horizontal conv + map, rows A and B ----------
#pragma unroll
        for (int r = 0; r < 2; ++r) {
            const int buf = bufA + r;
            float cv[4][4];
#pragma unroll
            for (int f = 0; f < 4; ++f) {
                float v[20];
#pragma unroll
                for (int q5 = 0; q5 < 5; ++q5) {
                    float4 t = *reinterpret_cast<const float4*>(
                        &vsbuf[buf][f][c0 + 4 * q5]);
                    v[4 * q5 + 0] = t.x; v[4 * q5 + 1] = t.y;
                    v[4 * q5 + 2] = t.z; v[4 * q5 + 3] = t.w;
                }
#pragma unroll
                for (int j = 0; j < 4; ++j) {
                    float s = KW[5] * v[8 + j];
#pragma unroll
                    for (int k = 0; k < 11; ++k) {
                        if (k == 5) continue;
                        s += KW[k] * v[3 + j + k];
                    }
                    cv[f][j] = s;
                }
            }
#pragma unroll
            for (int q = 0; q < 2; ++q) {
                u64 m1 = pk2(cv[0][2 * q], cv[0][2 * q + 1]);
                u64 m2 = pk2(cv[1][2 * q], cv[1][2 * q + 1]);
                u64 q2 = pk2(cv[2][2 * q], cv[2][2 * q + 1]);
                u64 rr = pk2(cv[3][2 * q], cv[3][2 * q + 1]);
                u64 m12 = f2mul(m1, m2);
                u64 sms = f2fma(m2, m2, f2mul(m1, m1));
                u64 num1 = f2fma(TWO, m12, C1);
                u64 sig12 = f2fma(m12, NEG1, rr);
                u64 num2 = f2fma(TWO, sig12, C2);
                u64 den1 = f2add(sms, C1);
                u64 den2 = f2add(f2fma(sms, NEG1, q2), C2);
                u64 num = f2mul(num1, num2);
                u64 den = f2mul(den1, den2);
                float n0, n1, d0, d1;
                upk2(num, n0, n1);
                upk2(den, d0, d1);
                acc += __fdividef(n0, d0);
                acc += __fdividef(n1, d1);
            }
        }
        // no trailing barrier: next pair writes the other buffer set; reuse
        // of this set is fenced by the next __syncthreads.
    }

    // block reduction -> per-block partial
#pragma unroll
    for (int o = 16; o > 0; o >>= 1)
        acc += __shfl_down_sync(0xFFFFFFFFu, acc, o);

    __shared__ float wsum[4];
    __shared__ int is_last;
    if ((tid & 31) == 0) wsum[tid >> 5] = acc;
    __syncthreads();
    if (tid == 0) {
        double s = (double)wsum[0] + (double)wsum[1] + (double)wsum[2] +
                   (double)wsum[3];
        g_partial[blockIdx.y * GX + blockIdx.x] = s;
        __threadfence();
        unsigned old = atomicInc(&g_count, NBLOCKS - 1);  // wraps to 0
        is_last = (old == NBLOCKS - 1);
    }
    __syncthreads();

    // last block finalizes (replay-deterministic: counter wraps to 0)
    if (is_last) {
        __threadfence();
        double s = 0.0;
        for (int i2 = tid; i2 < NBLOCKS; i2 += NTHREADS)
            s += __ldcg(&g_partial[i2]);
#pragma unroll
        for (int o = 16; o > 0; o >>= 1)
            s += __shfl_down_sync(0xFFFFFFFFu, s, o);
        __shared__ double dsm[4];
        if ((tid & 31) == 0) dsm[tid >> 5] = s;
        __syncthreads();
        if (tid == 0) {
            double tot = dsm[0] + dsm[1] + dsm[2] + dsm[3];
            out[0] = (float)(1.0 - tot / NPIX);
        }
    }
}

extern "C" void kernel_launch(void* const* d_in, const int* in_sizes, int n_in,
                              void* d_out, int out_size) {
    const float* sr = (const float*)d_in[0];
    const float* hr = (const float*)d_in[1];
    float* out = (float*)d_out;

    dim3 grid(GX, GY);
    ssim_kernel<<<grid, NTHREADS>>>(sr, hr, out);
}